// round 15
// baseline (speedup 1.0000x reference)
#include <cuda_runtime.h>
#include <cuda_fp16.h>
#include <math.h>
#include <stdint.h>

// ---------------- problem constants ----------------
#define B_    2
#define T_    1024
#define C_    1024
#define H_    16
#define HD_   64
#define DC_   256
#define DC1_  256
#define DR_   32
#define DN_   32
#define V_    32000
#define L_    4
#define NTOK  (B_*T_)             // 2048
#define DOWNW (DC_+DC1_+DR_)      // 544
#define WDP   640                 // padded wd output width
#define KVW   (H_*(DN_+HD_))      // 1536
#define EPS_  1.1920929e-07f

// ---------------- fp32 scratch ----------------
__device__ float g_x   [NTOK*C_];
__device__ float g_x0  [NTOK*C_];
__device__ float g_xn  [NTOK*C_];
__device__ float g_down[NTOK*DOWNW];
__device__ float g_kv  [NTOK*KVW];
__device__ float g_qpre[NTOK*C_];

// ---------------- fp16 hi/lo planes ----------------
__device__ __half g_wd_h  [L_*C_*WDP],    g_wd_l  [L_*C_*WDP];
__device__ __half g_wukv_h[L_*DC_*KVW],   g_wukv_l[L_*DC_*KVW];
__device__ __half g_wuq_h [L_*DC1_*C_],   g_wuq_l [L_*DC1_*C_];
__device__ __half g_ap_h  [L_*C_*C_],     g_ap_l  [L_*C_*C_];
__device__ __half g_fc_h  [L_*C_*4*C_],   g_fc_l  [L_*C_*4*C_];
__device__ __half g_pj_h  [L_*4*C_*C_],   g_pj_l  [L_*4*C_*C_];
__device__ __half g_lmh_h [C_*V_],        g_lmh_l [C_*V_];
__device__ __half g_xn_h  [NTOK*C_],      g_xn_l  [NTOK*C_];
__device__ __half g_dn_h  [NTOK*DOWNW],   g_dn_l  [NTOK*DOWNW];
__device__ __half g_y_h   [NTOK*C_],      g_y_l   [NTOK*C_];
__device__ __half g_h_h   [NTOK*4*C_],    g_h_l   [NTOK*4*C_];
__device__ __half g_q_h   [NTOK*C_],      g_q_l   [NTOK*C_];
__device__ __half g_k_h   [NTOK*C_],      g_k_l   [NTOK*C_];
__device__ __half g_v_h   [NTOK*C_],      g_v_l   [NTOK*C_];

// ---------------- helpers ----------------
__device__ __forceinline__ uint32_t smem_u32(const void* p) {
    uint32_t a;
    asm("{ .reg .u64 t; cvta.to.shared.u64 t, %1; cvt.u32.u64 %0, t; }" : "=r"(a) : "l"(p));
    return a;
}
__device__ __forceinline__ float warp_sum(float v) {
    v += __shfl_xor_sync(0xffffffffu, v, 16);
    v += __shfl_xor_sync(0xffffffffu, v, 8);
    v += __shfl_xor_sync(0xffffffffu, v, 4);
    v += __shfl_xor_sync(0xffffffffu, v, 2);
    v += __shfl_xor_sync(0xffffffffu, v, 1);
    return v;
}
__device__ __forceinline__ float block_sum(float v) {
    __shared__ float sh[32];
    int lane = threadIdx.x & 31, wid = threadIdx.x >> 5;
    v = warp_sum(v);
    if (lane == 0) sh[wid] = v;
    __syncthreads();
    int nw = blockDim.x >> 5;
    if (wid == 0) {
        float t = (lane < nw) ? sh[lane] : 0.f;
        t = warp_sum(t);
        if (lane == 0) sh[0] = t;
    }
    __syncthreads();
    return sh[0];
}
__device__ __forceinline__ void splith(float x, __half& hi, __half& lo) {
    hi = __float2half_rn(x);
    lo = __float2half_rn(x - __half2float(hi));
}
__device__ __forceinline__ uint32_t packh2(__half a, __half b) {
    return (uint32_t)__half_as_ushort(a) | ((uint32_t)__half_as_ushort(b) << 16);
}
__device__ __forceinline__ void splith2(float x, float y, uint32_t& hi, uint32_t& lo) {
    __half2 hh = __float22half2_rn(make_float2(x, y));
    float2 back = __half22float2(hh);
    __half2 ll = __float22half2_rn(make_float2(x - back.x, y - back.y));
    hi = *reinterpret_cast<uint32_t*>(&hh);
    lo = *reinterpret_cast<uint32_t*>(&ll);
}

// ---------------- mma / ldmatrix / cp.async wrappers ----------------
__device__ __forceinline__ void ldsm_x4(uint32_t* r, uint32_t addr) {
    asm volatile("ldmatrix.sync.aligned.m8n8.x4.shared.b16 {%0,%1,%2,%3}, [%4];"
                 : "=r"(r[0]), "=r"(r[1]), "=r"(r[2]), "=r"(r[3]) : "r"(addr));
}
__device__ __forceinline__ void ldsm_x4t(uint32_t* r, uint32_t addr) {
    asm volatile("ldmatrix.sync.aligned.m8n8.x4.trans.shared.b16 {%0,%1,%2,%3}, [%4];"
                 : "=r"(r[0]), "=r"(r[1]), "=r"(r[2]), "=r"(r[3]) : "r"(addr));
}
__device__ __forceinline__ void mma16816(float4& d, const uint32_t* a, uint32_t b0, uint32_t b1) {
    asm volatile(
        "mma.sync.aligned.m16n8k16.row.col.f32.f16.f16.f32 "
        "{%0,%1,%2,%3},{%4,%5,%6,%7},{%8,%9},{%0,%1,%2,%3};"
        : "+f"(d.x), "+f"(d.y), "+f"(d.z), "+f"(d.w)
        : "r"(a[0]), "r"(a[1]), "r"(a[2]), "r"(a[3]), "r"(b0), "r"(b1));
}
#define CP16(dst, src) \
    asm volatile("cp.async.cg.shared.global [%0], [%1], 16;" :: "r"(dst), "l"(src) : "memory")
#define CPCOMMIT() asm volatile("cp.async.commit_group;" ::: "memory")
#define CPWAITG(n) asm volatile("cp.async.wait_group " #n ";" ::: "memory")

// ---------------- split: 16 floats/thread, exact grid ----------------
__global__ void wsplit16(const float4* __restrict__ src,
                         uint4* __restrict__ hi, uint4* __restrict__ lo, long n16)
{
    long i = (long)blockIdx.x * blockDim.x + threadIdx.x;
    if (i >= n16) return;
    float4 f0 = src[4 * i];
    float4 f1 = src[4 * i + 1];
    float4 f2 = src[4 * i + 2];
    float4 f3 = src[4 * i + 3];
    uint4 h0, l0, h1, l1;
    splith2(f0.x, f0.y, h0.x, l0.x); splith2(f0.z, f0.w, h0.y, l0.y);
    splith2(f1.x, f1.y, h0.z, l0.z); splith2(f1.z, f1.w, h0.w, l0.w);
    splith2(f2.x, f2.y, h1.x, l1.x); splith2(f2.z, f2.w, h1.y, l1.y);
    splith2(f3.x, f3.y, h1.z, l1.z); splith2(f3.z, f3.w, h1.w, l1.w);
    hi[2 * i] = h0; hi[2 * i + 1] = h1;
    lo[2 * i] = l0; lo[2 * i + 1] = l1;
}

// ---------------- padded split, vectorized (wd only) --------------------
__global__ void wsplit_pad4(const float* __restrict__ src,
                            uint2* __restrict__ hi, uint2* __restrict__ lo, int n4)
{
    int stride = gridDim.x * blockDim.x;
    for (int i = blockIdx.x * blockDim.x + threadIdx.x; i < n4; i += stride) {
        int row = i / (WDP / 4);
        int c4  = i - row * (WDP / 4);
        float4 f = make_float4(0.f, 0.f, 0.f, 0.f);
        if (c4 < DOWNW / 4)
            f = *reinterpret_cast<const float4*>(src + (size_t)row * DOWNW + c4 * 4);
        uint2 h, l;
        splith2(f.x, f.y, h.x, l.x);
        splith2(f.z, f.w, h.y, l.y);
        hi[i] = h; lo[i] = l;
    }
}

// ---------------- embedding + rmsnorm ----------------
__global__ void embed_kernel(const int* __restrict__ idx, const float* __restrict__ wte) {
    int row = blockIdx.x;
    int tok = idx[row];
    const float* src = wte + (size_t)tok * C_;
    float s = 0.f;
    for (int i = threadIdx.x; i < C_; i += blockDim.x) { float v = src[i]; s += v * v; }
    s = block_sum(s);
    float r = rsqrtf(s * (1.0f / C_) + EPS_);
    for (int i = threadIdx.x; i < C_; i += blockDim.x) {
        float v = src[i] * r;
        g_x [(size_t)row * C_ + i] = v;
        g_x0[(size_t)row * C_ + i] = v;
    }
}

__global__ void mix_norm_kernel(const float* lr, const float* lx, int layer) {
    int row = blockIdx.x;
    float a = lr ? lr[layer] : 1.0f;
    float b = lx ? lx[layer] : 0.0f;
    float*       xr  = g_x  + (size_t)row * C_;
    const float* x0r = g_x0 + (size_t)row * C_;
    float s = 0.f;
    for (int i = threadIdx.x; i < C_; i += blockDim.x) {
        float v = a * xr[i] + b * x0r[i];
        xr[i] = v;
        s += v * v;
    }
    s = block_sum(s);
    float r = rsqrtf(s * (1.0f / C_) + EPS_);
    for (int i = threadIdx.x; i < C_; i += blockDim.x) {
        float v = xr[i] * r;
        g_xn[(size_t)row * C_ + i] = v;
        __half h, l;
        splith(v, h, l);
        g_xn_h[(size_t)row * C_ + i] = h;
        g_xn_l[(size_t)row * C_ + i] = l;
    }
}

// ---------------- 3xFP16 tensor-core GEMM v6 (templated M-tile) ----------
template<int MT>
__global__ __launch_bounds__(256, 2) void gemm_h4(
    const __half* __restrict__ Ah, const __half* __restrict__ Al,
    const __half* __restrict__ Bh, const __half* __restrict__ Bl,
    float* __restrict__ C, const float* __restrict__ D,
    __half* __restrict__ Chi, __half* __restrict__ Clo,
    int N, int K, int lda, int ldb, int ldc, int ldp, int mode, int nterms)
{
    constexpr int MI  = MT / 32;
    constexpr int APB = MT * 128;
    constexpr int STG = APB + 16384;

    extern __shared__ __align__(1024) char sm[];
    int tid = threadIdx.x;
    int wid = tid >> 5, lane = tid & 31;
    int warp_m = wid >> 2, warp_n = wid & 3;
    int m0 = blockIdx.x * MT, n0 = blockIdx.y * 128;
    uint32_t smb = smem_u32(sm);

    float4 acc[MI][4];
#pragma unroll
    for (int i = 0; i < MI; i++)
#pragma unroll
        for (int j = 0; j < 4; j++) acc[i][j] = make_float4(0.f, 0.f, 0.f, 0.f);

    int a_m   = tid >> 3;
    int a_hl  = (tid >> 2) & 1;
    int a_j   = tid & 3;
    int b_k0  = tid >> 4;
    int b_j   = tid & 15;
    const __half* Asel = a_hl ? Al : Ah;

    int arow0 = warp_m * (MT / 2) + (lane & 15);
    int akof  = (lane & 16);
    int bkr   = (lane & 15);
    int bco   = warp_n * 64 + ((lane >> 4) << 4);
    int ksrot = wid & 1;

    int nk = K >> 5;

    auto issue = [&](int kt, int stg) {
        uint32_t sA = smb + stg * STG;
        uint32_t sB = sA + APB;
#pragma unroll
        for (int r = 0; r < MT / 32; r++) {
            int m = a_m + r * 32;
            uint32_t off = (uint32_t)(m * 128 + a_hl * 64 + a_j * 16);
            off ^= (off >> 3) & 0x70;
            const __half* src = Asel + (size_t)(m0 + m) * lda + kt * 32 + a_j * 8;
            CP16(sA + off, src);
        }
#pragma unroll
        for (int r = 0; r < 4; r++) {
            int k = b_k0 + (r & 1) * 16;
            const __half* Bp = (r < 2) ? Bh : Bl;
            uint32_t off = ((uint32_t)(k * 256 + b_j * 16)) ^ ((uint32_t)(k & 7) << 4);
            off += (r < 2) ? 0u : 8192u;
            const __half* src = Bp + (size_t)(kt * 32 + k) * ldb + n0 + b_j * 8;
            CP16(sB + off, src);
        }
        CPCOMMIT();
    };

    issue(0, 0);
    issue(1, 1);

    for (int kt = 0; kt < nk; kt++) {
        if (kt == nk - 1) { CPWAITG(0); } else { CPWAITG(1); }
        __syncthreads();
        if (kt + 2 < nk) issue(kt + 2, (kt + 2) % 3);

        int s = kt % 3;
        uint32_t sA  = smb + s * STG;
        uint32_t sBh = sA + APB;
        uint32_t sBl = sBh + 8192;
#pragma unroll
        for (int ks0 = 0; ks0 < 2; ks0++) {
            int ks = ks0 ^ ksrot;
            uint32_t af[MI][4], bh[2][4], bl[2][4];
#pragma unroll
            for (int mi = 0; mi < MI; mi++) {
                uint32_t oh = (uint32_t)((arow0 + mi * 16) * 128 + ks * 32 + akof);
                oh ^= (oh >> 3) & 0x70;
                ldsm_x4(af[mi], sA + oh);
            }
#pragma unroll
            for (int nj = 0; nj < 2; nj++) {
                int krow = ks * 16 + bkr;
                uint32_t off = (uint32_t)(krow * 256 + bco + nj * 32) ^ ((uint32_t)(krow & 7) << 4);
                ldsm_x4t(bh[nj], sBh + off);
                ldsm_x4t(bl[nj], sBl + off);
            }
#pragma unroll
            for (int mi = 0; mi < MI; mi++)
#pragma unroll
                for (int ni = 0; ni < 4; ni++)
                    mma16816(acc[mi][ni], af[mi], bh[ni >> 1][(ni & 1) * 2], bh[ni >> 1][(ni & 1) * 2 + 1]);
#pragma unroll
            for (int mi = 0; mi < MI; mi++)
#pragma unroll
                for (int ni = 0; ni < 4; ni++)
                    mma16816(acc[mi][ni], af[mi], bl[ni >> 1][(ni & 1) * 2], bl[ni >> 1][(ni & 1) * 2 + 1]);
            if (nterms == 3) {
#pragma unroll
                for (int mi = 0; mi < MI; mi++) {
                    uint32_t ol = (uint32_t)((arow0 + mi * 16) * 128 + ks * 32 + akof + 64);
                    ol ^= (ol >> 3) & 0x70;
                    ldsm_x4(af[mi], sA + ol);
                }
#pragma unroll
                for (int mi = 0; mi < MI; mi++)
#pragma unroll
                    for (int ni = 0; ni < 4; ni++)
                        mma16816(acc[mi][ni], af[mi], bh[ni >> 1][(ni & 1) * 2], bh[ni >> 1][(ni & 1) * 2 + 1]);
            }
        }
    }

    int g = lane >> 2, t4 = lane & 3;
#pragma unroll
    for (int mi = 0; mi < MI; mi++) {
        int r0 = m0 + warp_m * (MT / 2) + mi * 16 + g;
#pragma unroll
        for (int ni = 0; ni < 4; ni++) {
            int col = n0 + warp_n * 32 + ni * 8 + 2 * t4;
            if (col >= N) continue;
            float4 v = acc[mi][ni];
            if (D) {
                float2 d0 = *reinterpret_cast<const float2*>(D + (size_t)r0 * ldc + col);
                float2 d1 = *reinterpret_cast<const float2*>(D + (size_t)(r0 + 8) * ldc + col);
                v.x += d0.x; v.y += d0.y; v.z += d1.x; v.w += d1.y;
            }
            if (mode == 1) {
                v.x = 15.0f * tanhf(v.x * (1.f / 15.f));
                v.y = 15.0f * tanhf(v.y * (1.f / 15.f));
                v.z = 15.0f * tanhf(v.z * (1.f / 15.f));
                v.w = 15.0f * tanhf(v.w * (1.f / 15.f));
            } else if (mode == 2) {
                v.x = (v.x > 0.f) ? v.x * v.x : 0.f;
                v.y = (v.y > 0.f) ? v.y * v.y : 0.f;
                v.z = (v.z > 0.f) ? v.z * v.z : 0.f;
                v.w = (v.w > 0.f) ? v.w * v.w : 0.f;
            }
            if (C) {
                *reinterpret_cast<float2*>(C + (size_t)r0 * ldc + col) = make_float2(v.x, v.y);
                *reinterpret_cast<float2*>(C + (size_t)(r0 + 8) * ldc + col) = make_float2(v.z, v.w);
            }
            if (Chi) {
                uint32_t ph0, pl0, ph1, pl1;
                splith2(v.x, v.y, ph0, pl0);
                splith2(v.z, v.w, ph1, pl1);
                *reinterpret_cast<uint32_t*>(Chi + (size_t)r0 * ldp + col)       = ph0;
                *reinterpret_cast<uint32_t*>(Clo + (size_t)r0 * ldp + col)       = pl0;
                *reinterpret_cast<uint32_t*>(Chi + (size_t)(r0 + 8) * ldp + col) = ph1;
                *reinterpret_cast<uint32_t*>(Clo + (size_t)(r0 + 8) * ldp + col) = pl1;
            }
        }
    }
}

// ---------------- per-token q/k/v build -> fp16 hi/lo planes --------------
__global__ void build_qkv_kernel(const int* __restrict__ idx,
                                 const float* __restrict__ cosp, const float* __restrict__ sinp,
                                 const float* __restrict__ vg, const float* __restrict__ vetab)
{
    int row = blockIdx.x;
    int h    = threadIdx.x >> 5;
    int lane = threadIdx.x & 31;
    const float* cosr = cosp + (size_t)row * (DR_ / 2);
    const float* sinr = sinp + (size_t)row * (DR_ / 2);

    float gv = g_xn[(size_t)row * C_ + lane] * vg[lane * H_ + h];
    gv = warp_sum(gv);
    float gate = 2.0f / (1.0f + __expf(-gv));

    int r16 = (lane < 16) ? lane : lane - 16;
    float c = cosr[r16], s = sinr[r16];
    size_t base = (size_t)row * C_ + h * 64;

    float kn = g_kv[(size_t)row * KVW + h * 96 + lane];
    const float* dro = g_down + (size_t)row * DOWNW + 512;
    float kr = (lane < 16) ? (dro[lane] * c + dro[lane + 16] * s)
                           : (-dro[lane - 16] * s + dro[lane] * c);
    float ssk = warp_sum(kn * kn + kr * kr);
    float rk = rsqrtf(ssk * (1.0f / 64.0f) + EPS_);
    __half hh_, ll_;
    splith(kn * rk, hh_, ll_);  g_k_h[base + lane]      = hh_; g_k_l[base + lane]      = ll_;
    splith(kr * rk, hh_, ll_);  g_k_h[base + lane + 32] = hh_; g_k_l[base + lane + 32] = ll_;

    const float* qp = g_qpre + (size_t)row * C_ + h * 64;
    float qn = qp[lane];
    float qr = (lane < 16) ? (qp[32 + lane] * c + qp[48 + lane] * s)
                           : (-qp[16 + lane] * s + qp[32 + lane] * c);
    float ssq = warp_sum(qn * qn + qr * qr);
    float rq = rsqrtf(ssq * (1.0f / 64.0f) + EPS_) * 0.125f;
    splith(qn * rq, hh_, ll_);  g_q_h[base + lane]      = hh_; g_q_l[base + lane]      = ll_;
    splith(qr * rq, hh_, ll_);  g_q_h[base + lane + 32] = hh_; g_q_l[base + lane + 32] = ll_;

    int tok = idx[row];
    const float* ver = vetab + (size_t)tok * C_ + h * 64;
    const float* kvv = g_kv + (size_t)row * KVW + h * 96 + 32;
    splith(kvv[lane]      + gate * ver[lane],      hh_, ll_);
    g_v_h[base + lane]      = hh_; g_v_l[base + lane]      = ll_;
    splith(kvv[lane + 32] + gate * ver[lane + 32], hh_, ll_);
    g_v_h[base + lane + 32] = hh_; g_v_l[base + lane + 32] = ll_;
}

// ---------------- tensor-core causal flash attention (double-buffered) ----
__global__ __launch_bounds__(128) void attn_mma()
{
    extern __shared__ __align__(1024) char dsm[];
    uint32_t smb = smem_u32(dsm);
    int tid = threadIdx.x;
    int wid = tid >> 5, lane = tid & 31;
    int q0 = (gridDim.x - 1 - blockIdx.x) * 64;
    int hh = blockIdx.y;
    int b  = blockIdx.z;
    int t4 = lane & 3, g = lane >> 2;

#pragma unroll
    for (int j = 0; j < 4; j++) {
        int idxq = tid + j * 128;
        int r = idxq >> 3, ch = idxq & 7;
        uint32_t off = (uint32_t)(r * 128 + ch * 16);
        off ^= (off >> 3) & 0x70;
        size_t src = (size_t)(b * T_ + q0 + r) * C_ + hh * 64 + ch * 8;
        CP16(smb + off,        g_q_h + src);
        CP16(smb + 8192 + off, g_q_l + src);
    }
    CPCOMMIT();

    auto issueKV = [&](int k0, int st) {
        uint32_t base = smb + 16384 + st * 32768;
#pragma unroll
        for (int j = 0; j < 4; j++) {
            int idxq = tid + j * 128;
            int r = idxq >> 3, ch = idxq & 7;
            uint32_t off = (uint32_t)(r * 128 + ch * 16);
            off ^= (off >> 3) & 0x70;
            size_t src = (size_t)(b * T_ + k0 + r) * C_ + hh * 64 + ch * 8;
            CP16(base + off,         g_k_h + src);
            CP16(base + 8192 + off,  g_k_l + src);
            CP16(base + 16384 + off, g_v_h + src);
            CP16(base + 24576 + off, g_v_l + src);
        }
        CPCOMMIT();
    };

    int nt = q0 / 64 + 1;
    issueKV(0, 0);

    CPWAITG(1);
    __syncthreads();

    int arow0 = wid * 16 + (lane & 15);
    int akof  = (lane & 16);
    uint32_t qh[4][4], ql[4][4];
#pragma unroll
    for (int ks = 0; ks < 4; ks++) {
        uint32_t off = (uint32_t)(arow0 * 128 + ks * 32 + akof);
        off ^= (off >> 3) & 0x70;
        ldsm_x4(qh[ks], smb + off);
        ldsm_x4(ql[ks], smb + 8192 + off);
    }

    float4 oacc[8];
#pragma unroll
    for (int i = 0; i < 8; i++) oacc[i] = make_float4(0.f, 0.f, 0.f, 0.f);
    float mrow0 = -1e30f, mrow1 = -1e30f, lrow0 = 0.f, lrow1 = 0.f;

    for (int t = 0; t < nt; t++) {
        if (t + 1 < nt) { issueKV((t + 1) * 64, (t + 1) & 1); CPWAITG(1); }
        else            { CPWAITG(0); }
        __syncthreads();

        uint32_t kb = smb + 16384 + (t & 1) * 32768;

        float4 sacc[8];
#pragma unroll
        for (int i = 0; i < 8; i++) sacc[i] = make_float4(0.f, 0.f, 0.f, 0.f);
#pragma unroll
        for (int ks = 0; ks < 4; ks++) {
#pragma unroll
            for (int njp = 0; njp < 4; njp++) {
                uint32_t kh[4], kl[4];
                uint32_t off = (uint32_t)(((lane & 15) + njp * 16) * 128 + ks * 32 + akof);
                off ^= (off >> 3) & 0x70;
                ldsm_x4(kh, kb + off);
                ldsm_x4(kl, kb + 8192 + off);
                mma16816(sacc[2 * njp],     qh[ks], kh[0], kh[2]);
                mma16816(sacc[2 * njp + 1], qh[ks], kh[1], kh[3]);
                mma16816(sacc[2 * njp],     qh[ks], kl[0], kl[2]);
                mma16816(sacc[2 * njp + 1], qh[ks], kl[1], kl[3]);
                mma16816(sacc[2 * njp],     ql[ks], kh[0], kh[2]);
                mma16816(sacc[2 * njp + 1], ql[ks], kh[1], kh[3]);
            }
        }

        if (t == nt - 1) {
            int qiA = wid * 16 + g, qiB = qiA + 8;
#pragma unroll
            for (int nj = 0; nj < 8; nj++) {
                int ki = nj * 8 + t4 * 2;
                if (ki     > qiA) sacc[nj].x = -1e30f;
                if (ki + 1 > qiA) sacc[nj].y = -1e30f;
                if (ki     > qiB) sacc[nj].z = -1e30f;
                if (ki + 1 > qiB) sacc[nj].w = -1e30f;
            }
        }

        float mx0 = -1e30f, mx1 = -1e30f;
#pragma unroll
        for (int nj = 0; nj < 8; nj++) {
            mx0 = fmaxf(mx0, fmaxf(sacc[nj].x, sacc[nj].y));
            mx1 = fmaxf(mx1, fmaxf(sacc[nj].z, sacc[nj].w));
        }
        mx0 = fmaxf(mx0, __shfl_xor_sync(0xffffffffu, mx0, 1));
        mx0 = fmaxf(mx0, __shfl_xor_sync(0xffffffffu, mx0, 2));
        mx1 = fmaxf(mx1, __shfl_xor_sync(0xffffffffu, mx1, 1));
        mx1 = fmaxf(mx1, __shfl_xor_sync(0xffffffffu, mx1, 2));
        float mn0 = fmaxf(mrow0, mx0), mn1 = fmaxf(mrow1, mx1);
        float c0 = __expf(mrow0 - mn0), c1 = __expf(mrow1 - mn1);
        float sum0 = 0.f, sum1 = 0.f;
#pragma unroll
        for (int nj = 0; nj < 8; nj++) {
            sacc[nj].x = __expf(sacc[nj].x - mn0);
            sacc[nj].y = __expf(sacc[nj].y - mn0);
            sacc[nj].z = __expf(sacc[nj].z - mn1);
            sacc[nj].w = __expf(sacc[nj].w - mn1);
            sum0 += sacc[nj].x + sacc[nj].y;
            sum1 += sacc[nj].z + sacc[nj].w;
        }
        sum0 += __shfl_xor_sync(0xffffffffu, sum0, 1);
        sum0 += __shfl_xor_sync(0xffffffffu, sum0, 2);
        sum1 += __shfl_xor_sync(0xffffffffu, sum1, 1);
        sum1 += __shfl_xor_sync(0xffffffffu, sum1, 2);
        lrow0 = lrow0 * c0 + sum0;
        lrow1 = lrow1 * c1 + sum1;
        mrow0 = mn0; mrow1 = mn1;
#pragma unroll
        for (int nd = 0; nd < 8; nd++) {
            oacc[nd].x *= c0; oacc[nd].y *= c0;
            oacc[nd].z *= c1; oacc[nd].w *= c1;
        }

#pragma unroll
        for (int kk = 0; kk < 4; kk++) {
            uint32_t ah[4], al[4];
            splith2(sacc[2*kk].x,   sacc[2*kk].y,   ah[0], al[0]);
            splith2(sacc[2*kk].z,   sacc[2*kk].w,   ah[1], al[1]);
            splith2(sacc[2*kk+1].x, sacc[2*kk+1].y, ah[2], al[2]);
            splith2(sacc[2*kk+1].z, sacc[2*kk+1].w, ah[3], al[3]);
#pragma unroll
            for (int ndp = 0; ndp < 4; ndp++) {
                uint32_t vh[4], vl[4];
                uint32_t off = (uint32_t)((kk * 16 + (lane & 15)) * 128 + ndp * 32 + akof);
                off ^= (off >> 3) & 0x70;
                ldsm_x4t(vh, kb + 16384 + off);
                ldsm_x4t(vl, kb + 24576 + off);
                mma16816(oacc[2 * ndp],     ah, vh[0], vh[1]);
                mma16816(oacc[2 * ndp + 1], ah, vh[2], vh[3]);
                mma16816(oacc[2 * ndp],     ah, vl[0], vl[1]);
                mma16816(oacc[2 * ndp + 1], ah, vl[2], vl[3]);
                mma16816(oacc[2 * ndp],     al, vh[0], vh[1]);
                mma16816(oacc[2 * ndp + 1], al, vh[2], vh[3]);
            }
        }
        __syncthreads();
    }

    float inv0 = 1.0f / lrow0, inv1 = 1.0f / lrow1;
    int r0 = q0 + wid * 16 + g, r1 = r0 + 8;
    size_t b0 = (size_t)(b * T_ + r0) * C_ + hh * 64;
    size_t b1 = (size_t)(b * T_ + r1) * C_ + hh * 64;
#pragma unroll
    for (int nd = 0; nd < 8; nd++) {
        int d = nd * 8 + t4 * 2;
        uint32_t ph, pl;
        splith2(oacc[nd].x * inv0, oacc[nd].y * inv0, ph, pl);
        *reinterpret_cast<uint32_t*>(g_y_h + b0 + d) = ph;
        *reinterpret_cast<uint32_t*>(g_y_l + b0 + d) = pl;
        splith2(oacc[nd].z * inv1, oacc[nd].w * inv1, ph, pl);
        *reinterpret_cast<uint32_t*>(g_y_h + b1 + d) = ph;
        *reinterpret_cast<uint32_t*>(g_y_l + b1 + d) = pl;
    }
}

// ---------------- host orchestration ----------------
extern "C" void kernel_launch(void* const* d_in, const int* in_sizes, int n_in,
                              void* d_out, int out_size)
{
    (void)in_sizes; (void)n_in; (void)out_size;
    const int*   idx  = (const int*)  d_in[0];
    const float* cosp = (const float*)d_in[1];
    const float* sinp = (const float*)d_in[2];
    const float* wte  = (const float*)d_in[3];
    const float* vemb = (const float*)d_in[4];
    const float* wd   = (const float*)d_in[5];
    const float* wukv = (const float*)d_in[6];
    const float* wuq  = (const float*)d_in[7];
    const float* vg   = (const float*)d_in[8];
    const float* ap   = (const float*)d_in[9];
    const float* fc   = (const float*)d_in[10];
    const float* pj   = (const float*)d_in[11];
    const float* lr   = (const float*)d_in[12];
    const float* lx   = (const float*)d_in[13];
    const float* lmh  = (const float*)d_in[14];
    float* out = (float*)d_out;

    float *px, *pdown, *pkv, *pqpre;
    cudaGetSymbolAddress((void**)&px,    g_x);
    cudaGetSymbolAddress((void**)&pdown, g_down);
    cudaGetSymbolAddress((void**)&pkv,   g_kv);
    cudaGetSymbolAddress((void**)&pqpre, g_qpre);

    __half *wd_h, *wd_l, *wukv_h, *wukv_l, *wuq_h, *wuq_l, *ap_h, *ap_l;
    __half *fc_h, *fc_l, *pj_h, *pj_l, *lmh_h, *lmh_l;
    __half *xn_h, *xn_l, *dn_h, *dn_l, *y_h, *y_l, *h_h, *h_l;
    cudaGetSymbolAddress((void**)&wd_h,   g_wd_h);   cudaGetSymbolAddress((void**)&wd_l,   g_wd_l);
    cudaGetSymbolAddress((void**)&wukv_h, g_wukv_h); cudaGetSymbolAddress((void**)&wukv_l, g_wukv_l);
    cudaGetSymbolAddress((void**)&wuq_h,  g_wuq_h);  cudaGetSymbolAddress((void**)&wuq_l,  g_wuq_l);
    cudaGetSymbolAddress((void**)&ap_h,   g_ap_h);   cudaGetSymbolAddress((void**)&ap_l,   g_ap_l);
    cudaGetSymbolAddress((void**)&fc_h,   g_fc_h);   cudaGetSymbolAddress((void**)&fc_l,   g_fc_l);
    cudaGetSymbolAddress((void**)&pj_h,   g_pj_h);   cudaGetSymbolAddress((void**)&pj_l,   g_pj_l);
    cudaGetSymbolAddress((void**)&lmh_h,  g_lmh_h);  cudaGetSymbolAddress((void**)&lmh_l,  g_lmh_l);
    cudaGetSymbolAddress((void**)&xn_h,   g_xn_h);   cudaGetSymbolAddress((void**)&xn_l,   g_xn_l);
    cudaGetSymbolAddress((void**)&dn_h,   g_dn_h);   cudaGetSymbolAddress((void**)&dn_l,   g_dn_l);
    cudaGetSymbolAddress((void**)&y_h,    g_y_h);    cudaGetSymbolAddress((void**)&y_l,    g_y_l);
    cudaGetSymbolAddress((void**)&h_h,    g_h_h);    cudaGetSymbolAddress((void**)&h_l,    g_h_l);

    const int SM128 = 3 * (128 * 128 + 16384);   // 96 KB
    const int SM64  = 3 * (64 * 128 + 16384);    // 72 KB
    cudaFuncSetAttribute(gemm_h4<128>, cudaFuncAttributeMaxDynamicSharedMemorySize, SM128);
    cudaFuncSetAttribute(gemm_h4<64>,  cudaFuncAttributeMaxDynamicSharedMemorySize, SM64);
    const int ASM = 81920;
    cudaFuncSetAttribute(attn_mma, cudaFuncAttributeMaxDynamicSharedMemorySize, ASM);

    // ---- side streams + events (host resources; device work identical per call) ----
    static cudaStream_t sA = nullptr, sB = nullptr;
    static cudaEvent_t evFork = nullptr, evEarly = nullptr, evBig = nullptr,
                       evDown = nullptr, evQ = nullptr;
    if (!sA) {
        cudaStreamCreateWithFlags(&sA, cudaStreamNonBlocking);
        cudaStreamCreateWithFlags(&sB, cudaStreamNonBlocking);
        cudaEventCreateWithFlags(&evFork,  cudaEventDisableTiming);
        cudaEventCreateWithFlags(&evEarly, cudaEventDisableTiming);
        cudaEventCreateWithFlags(&evBig,   cudaEventDisableTiming);
        cudaEventCreateWithFlags(&evDown,  cudaEventDisableTiming);
        cudaEventCreateWithFlags(&evQ,     cudaEventDisableTiming);
    }

    const int GM1 = NTOK / 128;   // 16
    const int GM2 = NTOK / 64;    // 32

    // ---- fork ----
    cudaEventRecord(evFork, 0);
    cudaStreamWaitEvent(sA, evFork, 0);
    cudaStreamWaitEvent(sB, evFork, 0);

    // early splits on sA (needed by down/kv/qpre)
    wsplit_pad4<<<2048, 256, 0, sA>>>(wd, (uint2*)wd_h, (uint2*)wd_l, L_ * C_ * WDP / 4);
    wsplit16<<<(int)((long)L_ * DC_ * KVW / 16 / 256), 256, 0, sA>>>(
        (const float4*)wukv, (uint4*)wukv_h, (uint4*)wukv_l, (long)L_ * DC_ * KVW / 16);
    wsplit16<<<(int)((long)L_ * DC1_ * C_ / 16 / 256), 256, 0, sA>>>(
        (const float4*)wuq, (uint4*)wuq_h, (uint4*)wuq_l, (long)L_ * DC1_ * C_ / 16);
    cudaEventRecord(evEarly, sA);

    // big splits on sB (needed from layer-0 ap/fc/pj and lm_head)
    wsplit16<<<(int)((long)L_ * C_ * C_ / 16 / 256), 256, 0, sB>>>(
        (const float4*)ap, (uint4*)ap_h, (uint4*)ap_l, (long)L_ * C_ * C_ / 16);
    wsplit16<<<(int)((long)L_ * C_ * 4 * C_ / 16 / 256), 256, 0, sB>>>(
        (const float4*)fc, (uint4*)fc_h, (uint4*)fc_l, (long)L_ * C_ * 4 * C_ / 16);
    wsplit16<<<(int)((long)L_ * 4 * C_ * C_ / 16 / 256), 256, 0, sB>>>(
        (const float4*)pj, (uint4*)pj_h, (uint4*)pj_l, (long)L_ * 4 * C_ * C_ / 16);
    wsplit16<<<(int)((long)C_ * V_ / 16 / 256), 256, 0, sB>>>(
        (const float4*)lmh, (uint4*)lmh_h, (uint4*)lmh_l, (long)C_ * V_ / 16);
    cudaEventRecord(evBig, sB);

    // main stream: embed + mix_norm overlap the early splits
    embed_kernel<<<NTOK, 256>>>(idx, wte);
    mix_norm_kernel<<<NTOK, 256>>>(lr, lx, 0);
    cudaStreamWaitEvent(0, evEarly, 0);

    for (int l = 0; l < L_; l++) {
        if (l > 0) mix_norm_kernel<<<NTOK, 256>>>(lr, lx, l);

        // down: MT=64, grid 32x5 = 160
        gemm_h4<64><<<dim3(GM2, WDP / 128), 256, SM64>>>(
            xn_h, xn_l, wd_h + (size_t)l * C_ * WDP, wd_l + (size_t)l * C_ * WDP,
            pdown, nullptr, dn_h, dn_l,
            DOWNW, C_, C_, WDP, DOWNW, DOWNW, 0, 3);
        cudaEventRecord(evDown, 0);

        // qpre on sA (parallel with kv on main)
        cudaStreamWaitEvent(sA, evDown, 0);
        gemm_h4<64><<<dim3(GM2, C_ / 128), 256, SM64, sA>>>(
            dn_h + DC_, dn_l + DC_, wuq_h + (size_t)l * DC1_ * C_, wuq_l + (size_t)l * DC1_ * C_,
            pqpre, nullptr, nullptr, nullptr,
            C_, DC1_, DOWNW, C_, C_, 0, 0, 3);
        cudaEventRecord(evQ, sA);

        // kv on main: MT=128, grid 16x12 = 192
        gemm_h4<128><<<dim3(GM1, KVW / 128), 256, SM128>>>(
            dn_h, dn_l, wukv_h + (size_t)l * DC_ * KVW, wukv_l + (size_t)l * DC_ * KVW,
            pkv, nullptr, nullptr, nullptr,
            KVW, DC_, DOWNW, KVW, KVW, 0, 0, 3);
        cudaStreamWaitEvent(0, evQ, 0);

        build_qkv_kernel<<<NTOK, 512>>>(idx, cosp, sinp,
                                        vg + (size_t)l * 32 * H_,
                                        vemb + (size_t)l * V_ * C_);

        attn_mma<<<dim3(T_ / 64, H_, B_), 128, ASM>>>();

        if (l == 0) cudaStreamWaitEvent(0, evBig, 0);   // join big splits

        // ap: MT=64, grid 32x8 = 256
        gemm_h4<64><<<dim3(GM2, C_ / 128), 256, SM64>>>(
            y_h, y_l, ap_h + (size_t)l * C_ * C_, ap_l + (size_t)l * C_ * C_,
            px, px, nullptr, nullptr,
            C_, C_, C_, C_, C_, 0, 0, 3);

        mix_norm_kernel<<<NTOK, 256>>>(nullptr, nullptr, 0);

        // fc: MT=128, grid 16x32 = 512
        gemm_h4<128><<<dim3(GM1, 4 * C_ / 128), 256, SM128>>>(
            xn_h, xn_l, fc_h + (size_t)l * C_ * 4 * C_, fc_l + (size_t)l * C_ * 4 * C_,
            nullptr, nullptr, h_h, h_l,
            4 * C_, C_, C_, 4 * C_, 0, 4 * C_, 2, 3);

        // pj: MT=64, grid 32x8 = 256
        gemm_h4<64><<<dim3(GM2, C_ / 128), 256, SM64>>>(
            h_h, h_l, pj_h + (size_t)l * 4 * C_ * C_, pj_l + (size_t)l * 4 * C_ * C_,
            px, px, nullptr, nullptr,
            C_, 4 * C_, 4 * C_, C_, C_, 0, 0, 3);
    }

    mix_norm_kernel<<<NTOK, 256>>>(nullptr, nullptr, 0);
    // lm_head: MT=128, grid 16x250 = 4000, 2-term
    gemm_h4<128><<<dim3(GM1, V_ / 128), 256, SM128>>>(
        xn_h, xn_l, lmh_h, lmh_l,
        out, nullptr, nullptr, nullptr,
        V_, C_, C_, V_, V_, 0, 1, 2);
}

// round 17
// speedup vs baseline: 1.0782x; 1.0782x over previous
#include <cuda_runtime.h>
#include <cuda_fp16.h>
#include <math.h>
#include <stdint.h>

// ---------------- problem constants ----------------
#define B_    2
#define T_    1024
#define C_    1024
#define H_    16
#define HD_   64
#define DC_   256
#define DC1_  256
#define DR_   32
#define DN_   32
#define V_    32000
#define L_    4
#define NTOK  (B_*T_)             // 2048
#define DOWNW (DC_+DC1_+DR_)      // 544
#define WDP   640                 // padded wd output width
#define KVW   (H_*(DN_+HD_))      // 1536
#define EPS_  1.1920929e-07f

// ---------------- fp32 scratch ----------------
__device__ float g_x   [NTOK*C_];
__device__ float g_x0  [NTOK*C_];
__device__ float g_xn  [NTOK*C_];
__device__ float g_down[NTOK*DOWNW];
__device__ float g_kv  [NTOK*KVW];
__device__ float g_qpre[NTOK*C_];

// ---------------- fp16 hi/lo planes ----------------
__device__ __half g_wd_h  [L_*C_*WDP],    g_wd_l  [L_*C_*WDP];
__device__ __half g_wukv_h[L_*DC_*KVW],   g_wukv_l[L_*DC_*KVW];
__device__ __half g_wuq_h [L_*DC1_*C_],   g_wuq_l [L_*DC1_*C_];
__device__ __half g_ap_h  [L_*C_*C_],     g_ap_l  [L_*C_*C_];
__device__ __half g_fc_h  [L_*C_*4*C_],   g_fc_l  [L_*C_*4*C_];
__device__ __half g_pj_h  [L_*4*C_*C_],   g_pj_l  [L_*4*C_*C_];
__device__ __half g_lmh_h [C_*V_],        g_lmh_l [C_*V_];
__device__ __half g_xn_h  [NTOK*C_],      g_xn_l  [NTOK*C_];
__device__ __half g_dn_h  [NTOK*DOWNW],   g_dn_l  [NTOK*DOWNW];
__device__ __half g_y_h   [NTOK*C_],      g_y_l   [NTOK*C_];
__device__ __half g_h_h   [NTOK*4*C_],    g_h_l   [NTOK*4*C_];
__device__ __half g_q_h   [NTOK*C_],      g_q_l   [NTOK*C_];
__device__ __half g_k_h   [NTOK*C_],      g_k_l   [NTOK*C_];
__device__ __half g_v_h   [NTOK*C_],      g_v_l   [NTOK*C_];

// ---------------- helpers ----------------
__device__ __forceinline__ uint32_t smem_u32(const void* p) {
    uint32_t a;
    asm("{ .reg .u64 t; cvta.to.shared.u64 t, %1; cvt.u32.u64 %0, t; }" : "=r"(a) : "l"(p));
    return a;
}
__device__ __forceinline__ float warp_sum(float v) {
    v += __shfl_xor_sync(0xffffffffu, v, 16);
    v += __shfl_xor_sync(0xffffffffu, v, 8);
    v += __shfl_xor_sync(0xffffffffu, v, 4);
    v += __shfl_xor_sync(0xffffffffu, v, 2);
    v += __shfl_xor_sync(0xffffffffu, v, 1);
    return v;
}
__device__ __forceinline__ float block_sum(float v) {
    __shared__ float sh[32];
    int lane = threadIdx.x & 31, wid = threadIdx.x >> 5;
    v = warp_sum(v);
    if (lane == 0) sh[wid] = v;
    __syncthreads();
    int nw = blockDim.x >> 5;
    if (wid == 0) {
        float t = (lane < nw) ? sh[lane] : 0.f;
        t = warp_sum(t);
        if (lane == 0) sh[0] = t;
    }
    __syncthreads();
    return sh[0];
}
__device__ __forceinline__ void splith(float x, __half& hi, __half& lo) {
    hi = __float2half_rn(x);
    lo = __float2half_rn(x - __half2float(hi));
}
__device__ __forceinline__ uint32_t packh2(__half a, __half b) {
    return (uint32_t)__half_as_ushort(a) | ((uint32_t)__half_as_ushort(b) << 16);
}
__device__ __forceinline__ void splith2(float x, float y, uint32_t& hi, uint32_t& lo) {
    __half2 hh = __float22half2_rn(make_float2(x, y));
    float2 back = __half22float2(hh);
    __half2 ll = __float22half2_rn(make_float2(x - back.x, y - back.y));
    hi = *reinterpret_cast<uint32_t*>(&hh);
    lo = *reinterpret_cast<uint32_t*>(&ll);
}

// ---------------- mma / ldmatrix / cp.async wrappers ----------------
__device__ __forceinline__ void ldsm_x4(uint32_t* r, uint32_t addr) {
    asm volatile("ldmatrix.sync.aligned.m8n8.x4.shared.b16 {%0,%1,%2,%3}, [%4];"
                 : "=r"(r[0]), "=r"(r[1]), "=r"(r[2]), "=r"(r[3]) : "r"(addr));
}
__device__ __forceinline__ void ldsm_x4t(uint32_t* r, uint32_t addr) {
    asm volatile("ldmatrix.sync.aligned.m8n8.x4.trans.shared.b16 {%0,%1,%2,%3}, [%4];"
                 : "=r"(r[0]), "=r"(r[1]), "=r"(r[2]), "=r"(r[3]) : "r"(addr));
}
__device__ __forceinline__ void mma16816(float4& d, const uint32_t* a, uint32_t b0, uint32_t b1) {
    asm volatile(
        "mma.sync.aligned.m16n8k16.row.col.f32.f16.f16.f32 "
        "{%0,%1,%2,%3},{%4,%5,%6,%7},{%8,%9},{%0,%1,%2,%3};"
        : "+f"(d.x), "+f"(d.y), "+f"(d.z), "+f"(d.w)
        : "r"(a[0]), "r"(a[1]), "r"(a[2]), "r"(a[3]), "r"(b0), "r"(b1));
}
#define CP16(dst, src) \
    asm volatile("cp.async.cg.shared.global [%0], [%1], 16;" :: "r"(dst), "l"(src) : "memory")
#define CPCOMMIT() asm volatile("cp.async.commit_group;" ::: "memory")
#define CPWAITG(n) asm volatile("cp.async.wait_group " #n ";" ::: "memory")

// ---------------- split: 16 floats/thread, exact grid ----------------
__global__ void wsplit16(const float4* __restrict__ src,
                         uint4* __restrict__ hi, uint4* __restrict__ lo, long n16)
{
    long i = (long)blockIdx.x * blockDim.x + threadIdx.x;
    if (i >= n16) return;
    float4 f0 = src[4 * i];
    float4 f1 = src[4 * i + 1];
    float4 f2 = src[4 * i + 2];
    float4 f3 = src[4 * i + 3];
    uint4 h0, l0, h1, l1;
    splith2(f0.x, f0.y, h0.x, l0.x); splith2(f0.z, f0.w, h0.y, l0.y);
    splith2(f1.x, f1.y, h0.z, l0.z); splith2(f1.z, f1.w, h0.w, l0.w);
    splith2(f2.x, f2.y, h1.x, l1.x); splith2(f2.z, f2.w, h1.y, l1.y);
    splith2(f3.x, f3.y, h1.z, l1.z); splith2(f3.z, f3.w, h1.w, l1.w);
    hi[2 * i] = h0; hi[2 * i + 1] = h1;
    lo[2 * i] = l0; lo[2 * i + 1] = l1;
}

// ---------------- padded split, vectorized (wd only) --------------------
__global__ void wsplit_pad4(const float* __restrict__ src,
                            uint2* __restrict__ hi, uint2* __restrict__ lo, int n4)
{
    int stride = gridDim.x * blockDim.x;
    for (int i = blockIdx.x * blockDim.x + threadIdx.x; i < n4; i += stride) {
        int row = i / (WDP / 4);
        int c4  = i - row * (WDP / 4);
        float4 f = make_float4(0.f, 0.f, 0.f, 0.f);
        if (c4 < DOWNW / 4)
            f = *reinterpret_cast<const float4*>(src + (size_t)row * DOWNW + c4 * 4);
        uint2 h, l;
        splith2(f.x, f.y, h.x, l.x);
        splith2(f.z, f.w, h.y, l.y);
        hi[i] = h; lo[i] = l;
    }
}

// ---------------- embedding + rmsnorm ----------------
__global__ void embed_kernel(const int* __restrict__ idx, const float* __restrict__ wte) {
    int row = blockIdx.x;
    int tok = idx[row];
    const float* src = wte + (size_t)tok * C_;
    float s = 0.f;
    for (int i = threadIdx.x; i < C_; i += blockDim.x) { float v = src[i]; s += v * v; }
    s = block_sum(s);
    float r = rsqrtf(s * (1.0f / C_) + EPS_);
    for (int i = threadIdx.x; i < C_; i += blockDim.x) {
        float v = src[i] * r;
        g_x [(size_t)row * C_ + i] = v;
        g_x0[(size_t)row * C_ + i] = v;
    }
}

__global__ void mix_norm_kernel(const float* lr, const float* lx, int layer) {
    int row = blockIdx.x;
    float a = lr ? lr[layer] : 1.0f;
    float b = lx ? lx[layer] : 0.0f;
    float*       xr  = g_x  + (size_t)row * C_;
    const float* x0r = g_x0 + (size_t)row * C_;
    float s = 0.f;
    for (int i = threadIdx.x; i < C_; i += blockDim.x) {
        float v = a * xr[i] + b * x0r[i];
        xr[i] = v;
        s += v * v;
    }
    s = block_sum(s);
    float r = rsqrtf(s * (1.0f / C_) + EPS_);
    for (int i = threadIdx.x; i < C_; i += blockDim.x) {
        float v = xr[i] * r;
        g_xn[(size_t)row * C_ + i] = v;
        __half h, l;
        splith(v, h, l);
        g_xn_h[(size_t)row * C_ + i] = h;
        g_xn_l[(size_t)row * C_ + i] = l;
    }
}

// ---------------- 3xFP16 tensor-core GEMM v6 (templated M-tile) ----------
template<int MT>
__global__ __launch_bounds__(256, 2) void gemm_h4(
    const __half* __restrict__ Ah, const __half* __restrict__ Al,
    const __half* __restrict__ Bh, const __half* __restrict__ Bl,
    float* __restrict__ C, const float* __restrict__ D,
    __half* __restrict__ Chi, __half* __restrict__ Clo,
    int N, int K, int lda, int ldb, int ldc, int ldp, int mode, int nterms)
{
    constexpr int MI  = MT / 32;
    constexpr int APB = MT * 128;
    constexpr int STG = APB + 16384;

    extern __shared__ __align__(1024) char sm[];
    int tid = threadIdx.x;
    int wid = tid >> 5, lane = tid & 31;
    int warp_m = wid >> 2, warp_n = wid & 3;
    int m0 = blockIdx.x * MT, n0 = blockIdx.y * 128;
    uint32_t smb = smem_u32(sm);

    float4 acc[MI][4];
#pragma unroll
    for (int i = 0; i < MI; i++)
#pragma unroll
        for (int j = 0; j < 4; j++) acc[i][j] = make_float4(0.f, 0.f, 0.f, 0.f);

    int a_m   = tid >> 3;
    int a_hl  = (tid >> 2) & 1;
    int a_j   = tid & 3;
    int b_k0  = tid >> 4;
    int b_j   = tid & 15;
    const __half* Asel = a_hl ? Al : Ah;

    int arow0 = warp_m * (MT / 2) + (lane & 15);
    int akof  = (lane & 16);
    int bkr   = (lane & 15);
    int bco   = warp_n * 64 + ((lane >> 4) << 4);
    int ksrot = wid & 1;

    int nk = K >> 5;

    auto issue = [&](int kt, int stg) {
        uint32_t sA = smb + stg * STG;
        uint32_t sB = sA + APB;
#pragma unroll
        for (int r = 0; r < MT / 32; r++) {
            int m = a_m + r * 32;
            uint32_t off = (uint32_t)(m * 128 + a_hl * 64 + a_j * 16);
            off ^= (off >> 3) & 0x70;
            const __half* src = Asel + (size_t)(m0 + m) * lda + kt * 32 + a_j * 8;
            CP16(sA + off, src);
        }
#pragma unroll
        for (int r = 0; r < 4; r++) {
            int k = b_k0 + (r & 1) * 16;
            const __half* Bp = (r < 2) ? Bh : Bl;
            uint32_t off = ((uint32_t)(k * 256 + b_j * 16)) ^ ((uint32_t)(k & 7) << 4);
            off += (r < 2) ? 0u : 8192u;
            const __half* src = Bp + (size_t)(kt * 32 + k) * ldb + n0 + b_j * 8;
            CP16(sB + off, src);
        }
        CPCOMMIT();
    };

    issue(0, 0);
    issue(1, 1);

    for (int kt = 0; kt < nk; kt++) {
        if (kt == nk - 1) { CPWAITG(0); } else { CPWAITG(1); }
        __syncthreads();
        if (kt + 2 < nk) issue(kt + 2, (kt + 2) % 3);

        int s = kt % 3;
        uint32_t sA  = smb + s * STG;
        uint32_t sBh = sA + APB;
        uint32_t sBl = sBh + 8192;
#pragma unroll
        for (int ks0 = 0; ks0 < 2; ks0++) {
            int ks = ks0 ^ ksrot;
            uint32_t af[MI][4], bh[2][4], bl[2][4];
#pragma unroll
            for (int mi = 0; mi < MI; mi++) {
                uint32_t oh = (uint32_t)((arow0 + mi * 16) * 128 + ks * 32 + akof);
                oh ^= (oh >> 3) & 0x70;
                ldsm_x4(af[mi], sA + oh);
            }
#pragma unroll
            for (int nj = 0; nj < 2; nj++) {
                int krow = ks * 16 + bkr;
                uint32_t off = (uint32_t)(krow * 256 + bco + nj * 32) ^ ((uint32_t)(krow & 7) << 4);
                ldsm_x4t(bh[nj], sBh + off);
                ldsm_x4t(bl[nj], sBl + off);
            }
#pragma unroll
            for (int mi = 0; mi < MI; mi++)
#pragma unroll
                for (int ni = 0; ni < 4; ni++)
                    mma16816(acc[mi][ni], af[mi], bh[ni >> 1][(ni & 1) * 2], bh[ni >> 1][(ni & 1) * 2 + 1]);
#pragma unroll
            for (int mi = 0; mi < MI; mi++)
#pragma unroll
                for (int ni = 0; ni < 4; ni++)
                    mma16816(acc[mi][ni], af[mi], bl[ni >> 1][(ni & 1) * 2], bl[ni >> 1][(ni & 1) * 2 + 1]);
            if (nterms == 3) {
#pragma unroll
                for (int mi = 0; mi < MI; mi++) {
                    uint32_t ol = (uint32_t)((arow0 + mi * 16) * 128 + ks * 32 + akof + 64);
                    ol ^= (ol >> 3) & 0x70;
                    ldsm_x4(af[mi], sA + ol);
                }
#pragma unroll
                for (int mi = 0; mi < MI; mi++)
#pragma unroll
                    for (int ni = 0; ni < 4; ni++)
                        mma16816(acc[mi][ni], af[mi], bh[ni >> 1][(ni & 1) * 2], bh[ni >> 1][(ni & 1) * 2 + 1]);
            }
        }
    }

    int g = lane >> 2, t4 = lane & 3;
#pragma unroll
    for (int mi = 0; mi < MI; mi++) {
        int r0 = m0 + warp_m * (MT / 2) + mi * 16 + g;
#pragma unroll
        for (int ni = 0; ni < 4; ni++) {
            int col = n0 + warp_n * 32 + ni * 8 + 2 * t4;
            if (col >= N) continue;
            float4 v = acc[mi][ni];
            if (D) {
                float2 d0 = *reinterpret_cast<const float2*>(D + (size_t)r0 * ldc + col);
                float2 d1 = *reinterpret_cast<const float2*>(D + (size_t)(r0 + 8) * ldc + col);
                v.x += d0.x; v.y += d0.y; v.z += d1.x; v.w += d1.y;
            }
            if (mode == 1) {
                v.x = 15.0f * tanhf(v.x * (1.f / 15.f));
                v.y = 15.0f * tanhf(v.y * (1.f / 15.f));
                v.z = 15.0f * tanhf(v.z * (1.f / 15.f));
                v.w = 15.0f * tanhf(v.w * (1.f / 15.f));
            } else if (mode == 2) {
                v.x = (v.x > 0.f) ? v.x * v.x : 0.f;
                v.y = (v.y > 0.f) ? v.y * v.y : 0.f;
                v.z = (v.z > 0.f) ? v.z * v.z : 0.f;
                v.w = (v.w > 0.f) ? v.w * v.w : 0.f;
            }
            if (C) {
                *reinterpret_cast<float2*>(C + (size_t)r0 * ldc + col) = make_float2(v.x, v.y);
                *reinterpret_cast<float2*>(C + (size_t)(r0 + 8) * ldc + col) = make_float2(v.z, v.w);
            }
            if (Chi) {
                uint32_t ph0, pl0, ph1, pl1;
                splith2(v.x, v.y, ph0, pl0);
                splith2(v.z, v.w, ph1, pl1);
                *reinterpret_cast<uint32_t*>(Chi + (size_t)r0 * ldp + col)       = ph0;
                *reinterpret_cast<uint32_t*>(Clo + (size_t)r0 * ldp + col)       = pl0;
                *reinterpret_cast<uint32_t*>(Chi + (size_t)(r0 + 8) * ldp + col) = ph1;
                *reinterpret_cast<uint32_t*>(Clo + (size_t)(r0 + 8) * ldp + col) = pl1;
            }
        }
    }
}

// ---------------- per-token q/k/v build -> fp16 hi/lo planes --------------
__global__ void build_qkv_kernel(const int* __restrict__ idx,
                                 const float* __restrict__ cosp, const float* __restrict__ sinp,
                                 const float* __restrict__ vg, const float* __restrict__ vetab)
{
    int row = blockIdx.x;
    int h    = threadIdx.x >> 5;
    int lane = threadIdx.x & 31;
    const float* cosr = cosp + (size_t)row * (DR_ / 2);
    const float* sinr = sinp + (size_t)row * (DR_ / 2);

    float gv = g_xn[(size_t)row * C_ + lane] * vg[lane * H_ + h];
    gv = warp_sum(gv);
    float gate = 2.0f / (1.0f + __expf(-gv));

    int r16 = (lane < 16) ? lane : lane - 16;
    float c = cosr[r16], s = sinr[r16];
    size_t base = (size_t)row * C_ + h * 64;

    float kn = g_kv[(size_t)row * KVW + h * 96 + lane];
    const float* dro = g_down + (size_t)row * DOWNW + 512;
    float kr = (lane < 16) ? (dro[lane] * c + dro[lane + 16] * s)
                           : (-dro[lane - 16] * s + dro[lane] * c);
    float ssk = warp_sum(kn * kn + kr * kr);
    float rk = rsqrtf(ssk * (1.0f / 64.0f) + EPS_);
    __half hh_, ll_;
    splith(kn * rk, hh_, ll_);  g_k_h[base + lane]      = hh_; g_k_l[base + lane]      = ll_;
    splith(kr * rk, hh_, ll_);  g_k_h[base + lane + 32] = hh_; g_k_l[base + lane + 32] = ll_;

    const float* qp = g_qpre + (size_t)row * C_ + h * 64;
    float qn = qp[lane];
    float qr = (lane < 16) ? (qp[32 + lane] * c + qp[48 + lane] * s)
                           : (-qp[16 + lane] * s + qp[32 + lane] * c);
    float ssq = warp_sum(qn * qn + qr * qr);
    float rq = rsqrtf(ssq * (1.0f / 64.0f) + EPS_) * 0.125f;
    splith(qn * rq, hh_, ll_);  g_q_h[base + lane]      = hh_; g_q_l[base + lane]      = ll_;
    splith(qr * rq, hh_, ll_);  g_q_h[base + lane + 32] = hh_; g_q_l[base + lane + 32] = ll_;

    int tok = idx[row];
    const float* ver = vetab + (size_t)tok * C_ + h * 64;
    const float* kvv = g_kv + (size_t)row * KVW + h * 96 + 32;
    splith(kvv[lane]      + gate * ver[lane],      hh_, ll_);
    g_v_h[base + lane]      = hh_; g_v_l[base + lane]      = ll_;
    splith(kvv[lane + 32] + gate * ver[lane + 32], hh_, ll_);
    g_v_h[base + lane + 32] = hh_; g_v_l[base + lane + 32] = ll_;
}

// ---------------- tensor-core causal flash attention (double-buffered) ----
__global__ __launch_bounds__(128) void attn_mma()
{
    extern __shared__ __align__(1024) char dsm[];
    uint32_t smb = smem_u32(dsm);
    int tid = threadIdx.x;
    int wid = tid >> 5, lane = tid & 31;
    int q0 = (gridDim.x - 1 - blockIdx.x) * 64;
    int hh = blockIdx.y;
    int b  = blockIdx.z;
    int t4 = lane & 3, g = lane >> 2;

#pragma unroll
    for (int j = 0; j < 4; j++) {
        int idxq = tid + j * 128;
        int r = idxq >> 3, ch = idxq & 7;
        uint32_t off = (uint32_t)(r * 128 + ch * 16);
        off ^= (off >> 3) & 0x70;
        size_t src = (size_t)(b * T_ + q0 + r) * C_ + hh * 64 + ch * 8;
        CP16(smb + off,        g_q_h + src);
        CP16(smb + 8192 + off, g_q_l + src);
    }
    CPCOMMIT();

    auto issueKV = [&](int k0, int st) {
        uint32_t base = smb + 16384 + st * 32768;
#pragma unroll
        for (int j = 0; j < 4; j++) {
            int idxq = tid + j * 128;
            int r = idxq >> 3, ch = idxq & 7;
            uint32_t off = (uint32_t)(r * 128 + ch * 16);
            off ^= (off >> 3) & 0x70;
            size_t src = (size_t)(b * T_ + k0 + r) * C_ + hh * 64 + ch * 8;
            CP16(base + off,         g_k_h + src);
            CP16(base + 8192 + off,  g_k_l + src);
            CP16(base + 16384 + off, g_v_h + src);
            CP16(base + 24576 + off, g_v_l + src);
        }
        CPCOMMIT();
    };

    int nt = q0 / 64 + 1;
    issueKV(0, 0);

    CPWAITG(1);
    __syncthreads();

    int arow0 = wid * 16 + (lane & 15);
    int akof  = (lane & 16);
    uint32_t qh[4][4], ql[4][4];
#pragma unroll
    for (int ks = 0; ks < 4; ks++) {
        uint32_t off = (uint32_t)(arow0 * 128 + ks * 32 + akof);
        off ^= (off >> 3) & 0x70;
        ldsm_x4(qh[ks], smb + off);
        ldsm_x4(ql[ks], smb + 8192 + off);
    }

    float4 oacc[8];
#pragma unroll
    for (int i = 0; i < 8; i++) oacc[i] = make_float4(0.f, 0.f, 0.f, 0.f);
    float mrow0 = -1e30f, mrow1 = -1e30f, lrow0 = 0.f, lrow1 = 0.f;

    for (int t = 0; t < nt; t++) {
        if (t + 1 < nt) { issueKV((t + 1) * 64, (t + 1) & 1); CPWAITG(1); }
        else            { CPWAITG(0); }
        __syncthreads();

        uint32_t kb = smb + 16384 + (t & 1) * 32768;

        float4 sacc[8];
#pragma unroll
        for (int i = 0; i < 8; i++) sacc[i] = make_float4(0.f, 0.f, 0.f, 0.f);
#pragma unroll
        for (int ks = 0; ks < 4; ks++) {
#pragma unroll
            for (int njp = 0; njp < 4; njp++) {
                uint32_t kh[4], kl[4];
                uint32_t off = (uint32_t)(((lane & 15) + njp * 16) * 128 + ks * 32 + akof);
                off ^= (off >> 3) & 0x70;
                ldsm_x4(kh, kb + off);
                ldsm_x4(kl, kb + 8192 + off);
                mma16816(sacc[2 * njp],     qh[ks], kh[0], kh[2]);
                mma16816(sacc[2 * njp + 1], qh[ks], kh[1], kh[3]);
                mma16816(sacc[2 * njp],     qh[ks], kl[0], kl[2]);
                mma16816(sacc[2 * njp + 1], qh[ks], kl[1], kl[3]);
                mma16816(sacc[2 * njp],     ql[ks], kh[0], kh[2]);
                mma16816(sacc[2 * njp + 1], ql[ks], kh[1], kh[3]);
            }
        }

        if (t == nt - 1) {
            int qiA = wid * 16 + g, qiB = qiA + 8;
#pragma unroll
            for (int nj = 0; nj < 8; nj++) {
                int ki = nj * 8 + t4 * 2;
                if (ki     > qiA) sacc[nj].x = -1e30f;
                if (ki + 1 > qiA) sacc[nj].y = -1e30f;
                if (ki     > qiB) sacc[nj].z = -1e30f;
                if (ki + 1 > qiB) sacc[nj].w = -1e30f;
            }
        }

        float mx0 = -1e30f, mx1 = -1e30f;
#pragma unroll
        for (int nj = 0; nj < 8; nj++) {
            mx0 = fmaxf(mx0, fmaxf(sacc[nj].x, sacc[nj].y));
            mx1 = fmaxf(mx1, fmaxf(sacc[nj].z, sacc[nj].w));
        }
        mx0 = fmaxf(mx0, __shfl_xor_sync(0xffffffffu, mx0, 1));
        mx0 = fmaxf(mx0, __shfl_xor_sync(0xffffffffu, mx0, 2));
        mx1 = fmaxf(mx1, __shfl_xor_sync(0xffffffffu, mx1, 1));
        mx1 = fmaxf(mx1, __shfl_xor_sync(0xffffffffu, mx1, 2));
        float mn0 = fmaxf(mrow0, mx0), mn1 = fmaxf(mrow1, mx1);
        float c0 = __expf(mrow0 - mn0), c1 = __expf(mrow1 - mn1);
        float sum0 = 0.f, sum1 = 0.f;
#pragma unroll
        for (int nj = 0; nj < 8; nj++) {
            sacc[nj].x = __expf(sacc[nj].x - mn0);
            sacc[nj].y = __expf(sacc[nj].y - mn0);
            sacc[nj].z = __expf(sacc[nj].z - mn1);
            sacc[nj].w = __expf(sacc[nj].w - mn1);
            sum0 += sacc[nj].x + sacc[nj].y;
            sum1 += sacc[nj].z + sacc[nj].w;
        }
        sum0 += __shfl_xor_sync(0xffffffffu, sum0, 1);
        sum0 += __shfl_xor_sync(0xffffffffu, sum0, 2);
        sum1 += __shfl_xor_sync(0xffffffffu, sum1, 1);
        sum1 += __shfl_xor_sync(0xffffffffu, sum1, 2);
        lrow0 = lrow0 * c0 + sum0;
        lrow1 = lrow1 * c1 + sum1;
        mrow0 = mn0; mrow1 = mn1;
#pragma unroll
        for (int nd = 0; nd < 8; nd++) {
            oacc[nd].x *= c0; oacc[nd].y *= c0;
            oacc[nd].z *= c1; oacc[nd].w *= c1;
        }

#pragma unroll
        for (int kk = 0; kk < 4; kk++) {
            uint32_t ah[4], al[4];
            splith2(sacc[2*kk].x,   sacc[2*kk].y,   ah[0], al[0]);
            splith2(sacc[2*kk].z,   sacc[2*kk].w,   ah[1], al[1]);
            splith2(sacc[2*kk+1].x, sacc[2*kk+1].y, ah[2], al[2]);
            splith2(sacc[2*kk+1].z, sacc[2*kk+1].w, ah[3], al[3]);
#pragma unroll
            for (int ndp = 0; ndp < 4; ndp++) {
                uint32_t vh[4], vl[4];
                uint32_t off = (uint32_t)((kk * 16 + (lane & 15)) * 128 + ndp * 32 + akof);
                off ^= (off >> 3) & 0x70;
                ldsm_x4t(vh, kb + 16384 + off);
                ldsm_x4t(vl, kb + 24576 + off);
                mma16816(oacc[2 * ndp],     ah, vh[0], vh[1]);
                mma16816(oacc[2 * ndp + 1], ah, vh[2], vh[3]);
                mma16816(oacc[2 * ndp],     ah, vl[0], vl[1]);
                mma16816(oacc[2 * ndp + 1], ah, vl[2], vl[3]);
                mma16816(oacc[2 * ndp],     al, vh[0], vh[1]);
                mma16816(oacc[2 * ndp + 1], al, vh[2], vh[3]);
            }
        }
        __syncthreads();
    }

    float inv0 = 1.0f / lrow0, inv1 = 1.0f / lrow1;
    int r0 = q0 + wid * 16 + g, r1 = r0 + 8;
    size_t b0 = (size_t)(b * T_ + r0) * C_ + hh * 64;
    size_t b1 = (size_t)(b * T_ + r1) * C_ + hh * 64;
#pragma unroll
    for (int nd = 0; nd < 8; nd++) {
        int d = nd * 8 + t4 * 2;
        uint32_t ph, pl;
        splith2(oacc[nd].x * inv0, oacc[nd].y * inv0, ph, pl);
        *reinterpret_cast<uint32_t*>(g_y_h + b0 + d) = ph;
        *reinterpret_cast<uint32_t*>(g_y_l + b0 + d) = pl;
        splith2(oacc[nd].z * inv1, oacc[nd].w * inv1, ph, pl);
        *reinterpret_cast<uint32_t*>(g_y_h + b1 + d) = ph;
        *reinterpret_cast<uint32_t*>(g_y_l + b1 + d) = pl;
    }
}

// ---------------- host orchestration ----------------
extern "C" void kernel_launch(void* const* d_in, const int* in_sizes, int n_in,
                              void* d_out, int out_size)
{
    (void)in_sizes; (void)n_in; (void)out_size;
    const int*   idx  = (const int*)  d_in[0];
    const float* cosp = (const float*)d_in[1];
    const float* sinp = (const float*)d_in[2];
    const float* wte  = (const float*)d_in[3];
    const float* vemb = (const float*)d_in[4];
    const float* wd   = (const float*)d_in[5];
    const float* wukv = (const float*)d_in[6];
    const float* wuq  = (const float*)d_in[7];
    const float* vg   = (const float*)d_in[8];
    const float* ap   = (const float*)d_in[9];
    const float* fc   = (const float*)d_in[10];
    const float* pj   = (const float*)d_in[11];
    const float* lr   = (const float*)d_in[12];
    const float* lx   = (const float*)d_in[13];
    const float* lmh  = (const float*)d_in[14];
    float* out = (float*)d_out;

    float *px, *pdown, *pkv, *pqpre;
    cudaGetSymbolAddress((void**)&px,    g_x);
    cudaGetSymbolAddress((void**)&pdown, g_down);
    cudaGetSymbolAddress((void**)&pkv,   g_kv);
    cudaGetSymbolAddress((void**)&pqpre, g_qpre);

    __half *wd_h, *wd_l, *wukv_h, *wukv_l, *wuq_h, *wuq_l, *ap_h, *ap_l;
    __half *fc_h, *fc_l, *pj_h, *pj_l, *lmh_h, *lmh_l;
    __half *xn_h, *xn_l, *dn_h, *dn_l, *y_h, *y_l, *h_h, *h_l;
    cudaGetSymbolAddress((void**)&wd_h,   g_wd_h);   cudaGetSymbolAddress((void**)&wd_l,   g_wd_l);
    cudaGetSymbolAddress((void**)&wukv_h, g_wukv_h); cudaGetSymbolAddress((void**)&wukv_l, g_wukv_l);
    cudaGetSymbolAddress((void**)&wuq_h,  g_wuq_h);  cudaGetSymbolAddress((void**)&wuq_l,  g_wuq_l);
    cudaGetSymbolAddress((void**)&ap_h,   g_ap_h);   cudaGetSymbolAddress((void**)&ap_l,   g_ap_l);
    cudaGetSymbolAddress((void**)&fc_h,   g_fc_h);   cudaGetSymbolAddress((void**)&fc_l,   g_fc_l);
    cudaGetSymbolAddress((void**)&pj_h,   g_pj_h);   cudaGetSymbolAddress((void**)&pj_l,   g_pj_l);
    cudaGetSymbolAddress((void**)&lmh_h,  g_lmh_h);  cudaGetSymbolAddress((void**)&lmh_l,  g_lmh_l);
    cudaGetSymbolAddress((void**)&xn_h,   g_xn_h);   cudaGetSymbolAddress((void**)&xn_l,   g_xn_l);
    cudaGetSymbolAddress((void**)&dn_h,   g_dn_h);   cudaGetSymbolAddress((void**)&dn_l,   g_dn_l);
    cudaGetSymbolAddress((void**)&y_h,    g_y_h);    cudaGetSymbolAddress((void**)&y_l,    g_y_l);
    cudaGetSymbolAddress((void**)&h_h,    g_h_h);    cudaGetSymbolAddress((void**)&h_l,    g_h_l);

    const int SM128 = 3 * (128 * 128 + 16384);   // 96 KB
    const int SM64  = 3 * (64 * 128 + 16384);    // 72 KB
    cudaFuncSetAttribute(gemm_h4<128>, cudaFuncAttributeMaxDynamicSharedMemorySize, SM128);
    cudaFuncSetAttribute(gemm_h4<64>,  cudaFuncAttributeMaxDynamicSharedMemorySize, SM64);
    const int ASM = 81920;
    cudaFuncSetAttribute(attn_mma, cudaFuncAttributeMaxDynamicSharedMemorySize, ASM);

    // ---- side streams + events ----
    static cudaStream_t sA = nullptr, sB = nullptr;
    static cudaEvent_t evFork = nullptr, evEarly = nullptr, evBig = nullptr,
                       evDown = nullptr, evQ = nullptr;
    if (!sA) {
        cudaStreamCreateWithFlags(&sA, cudaStreamNonBlocking);
        cudaStreamCreateWithFlags(&sB, cudaStreamNonBlocking);
        cudaEventCreateWithFlags(&evFork,  cudaEventDisableTiming);
        cudaEventCreateWithFlags(&evEarly, cudaEventDisableTiming);
        cudaEventCreateWithFlags(&evBig,   cudaEventDisableTiming);
        cudaEventCreateWithFlags(&evDown,  cudaEventDisableTiming);
        cudaEventCreateWithFlags(&evQ,     cudaEventDisableTiming);
    }

    const int GM1 = NTOK / 128;   // 16
    const int GM2 = NTOK / 64;    // 32

    // ---- fork ----
    cudaEventRecord(evFork, 0);
    cudaStreamWaitEvent(sA, evFork, 0);
    cudaStreamWaitEvent(sB, evFork, 0);

    // early splits on sA
    wsplit_pad4<<<2048, 256, 0, sA>>>(wd, (uint2*)wd_h, (uint2*)wd_l, L_ * C_ * WDP / 4);
    wsplit16<<<(int)((long)L_ * DC_ * KVW / 16 / 256), 256, 0, sA>>>(
        (const float4*)wukv, (uint4*)wukv_h, (uint4*)wukv_l, (long)L_ * DC_ * KVW / 16);
    wsplit16<<<(int)((long)L_ * DC1_ * C_ / 16 / 256), 256, 0, sA>>>(
        (const float4*)wuq, (uint4*)wuq_h, (uint4*)wuq_l, (long)L_ * DC1_ * C_ / 16);
    cudaEventRecord(evEarly, sA);

    // big splits on sB
    wsplit16<<<(int)((long)L_ * C_ * C_ / 16 / 256), 256, 0, sB>>>(
        (const float4*)ap, (uint4*)ap_h, (uint4*)ap_l, (long)L_ * C_ * C_ / 16);
    wsplit16<<<(int)((long)L_ * C_ * 4 * C_ / 16 / 256), 256, 0, sB>>>(
        (const float4*)fc, (uint4*)fc_h, (uint4*)fc_l, (long)L_ * C_ * 4 * C_ / 16);
    wsplit16<<<(int)((long)L_ * 4 * C_ * C_ / 16 / 256), 256, 0, sB>>>(
        (const float4*)pj, (uint4*)pj_h, (uint4*)pj_l, (long)L_ * 4 * C_ * C_ / 16);
    wsplit16<<<(int)((long)C_ * V_ / 16 / 256), 256, 0, sB>>>(
        (const float4*)lmh, (uint4*)lmh_h, (uint4*)lmh_l, (long)C_ * V_ / 16);
    cudaEventRecord(evBig, sB);

    // main stream
    embed_kernel<<<NTOK, 256>>>(idx, wte);
    mix_norm_kernel<<<NTOK, 256>>>(lr, lx, 0);
    cudaStreamWaitEvent(0, evEarly, 0);

    for (int l = 0; l < L_; l++) {
        if (l > 0) mix_norm_kernel<<<NTOK, 256>>>(lr, lx, l);

        // down: MT=64, 3-term
        gemm_h4<64><<<dim3(GM2, WDP / 128), 256, SM64>>>(
            xn_h, xn_l, wd_h + (size_t)l * C_ * WDP, wd_l + (size_t)l * C_ * WDP,
            pdown, nullptr, dn_h, dn_l,
            DOWNW, C_, C_, WDP, DOWNW, DOWNW, 0, 3);
        cudaEventRecord(evDown, 0);

        // qpre on sA (parallel with kv on main), 3-term
        cudaStreamWaitEvent(sA, evDown, 0);
        gemm_h4<64><<<dim3(GM2, C_ / 128), 256, SM64, sA>>>(
            dn_h + DC_, dn_l + DC_, wuq_h + (size_t)l * DC1_ * C_, wuq_l + (size_t)l * DC1_ * C_,
            pqpre, nullptr, nullptr, nullptr,
            C_, DC1_, DOWNW, C_, C_, 0, 0, 3);
        cudaEventRecord(evQ, sA);

        // kv on main, 3-term
        gemm_h4<128><<<dim3(GM1, KVW / 128), 256, SM128>>>(
            dn_h, dn_l, wukv_h + (size_t)l * DC_ * KVW, wukv_l + (size_t)l * DC_ * KVW,
            pkv, nullptr, nullptr, nullptr,
            KVW, DC_, DOWNW, KVW, KVW, 0, 0, 3);
        cudaStreamWaitEvent(0, evQ, 0);

        build_qkv_kernel<<<NTOK, 512>>>(idx, cosp, sinp,
                                        vg + (size_t)l * 32 * H_,
                                        vemb + (size_t)l * V_ * C_);

        attn_mma<<<dim3(T_ / 64, H_, B_), 128, ASM>>>();

        if (l == 0) cudaStreamWaitEvent(0, evBig, 0);

        // ap: MT=64, 2-term (activation-residual term dropped; residual increment)
        gemm_h4<64><<<dim3(GM2, C_ / 128), 256, SM64>>>(
            y_h, y_l, ap_h + (size_t)l * C_ * C_, ap_l + (size_t)l * C_ * C_,
            px, px, nullptr, nullptr,
            C_, C_, C_, C_, C_, 0, 0, 2);

        mix_norm_kernel<<<NTOK, 256>>>(nullptr, nullptr, 0);

        // fc: MT=128, 3-term (relu^2 doubles error sensitivity — keep full)
        gemm_h4<128><<<dim3(GM1, 4 * C_ / 128), 256, SM128>>>(
            xn_h, xn_l, fc_h + (size_t)l * C_ * 4 * C_, fc_l + (size_t)l * C_ * 4 * C_,
            nullptr, nullptr, h_h, h_l,
            4 * C_, C_, C_, 4 * C_, 0, 4 * C_, 2, 3);

        // pj: MT=64, 2-term (activation-residual term dropped)
        gemm_h4<64><<<dim3(GM2, C_ / 128), 256, SM64>>>(
            h_h, h_l, pj_h + (size_t)l * 4 * C_ * C_, pj_l + (size_t)l * 4 * C_ * C_,
            px, px, nullptr, nullptr,
            C_, 4 * C_, 4 * C_, C_, C_, 0, 0, 2);
    }

    mix_norm_kernel<<<NTOK, 256>>>(nullptr, nullptr, 0);
    // lm_head: MT=128, 2-term
    gemm_h4<128><<<dim3(GM1, V_ / 128), 256, SM128>>>(
        xn_h, xn_l, lmh_h, lmh_l,
        out, nullptr, nullptr, nullptr,
        V_, C_, C_, V_, V_, 0, 1, 2);
}